// round 2
// baseline (speedup 1.0000x reference)
#include <cuda_runtime.h>
#include <cstdint>
#include <cstddef>

// ---------------- problem constants ----------------
#define BQ    2
#define S_LEN 2048
#define DM    5120
#define NH    32
#define NKV   8
#define HDIM  128
#define QDIM  (NH * HDIM)    // 4096
#define KVDIM (NKV * HDIM)   // 1024
#define GRP   (NH / NKV)     // 4
#define ATT_SCALE 0.08838834764831845f
#define LN_BASE 13.815510557964274f   // ln(1e6)

// ---------------- scratch (device globals; allocation-free rule) ----------------
__device__ float g_q[(size_t)BQ * S_LEN * QDIM];            // 67 MB
__device__ float g_k[(size_t)BQ * S_LEN * KVDIM];           // 17 MB
__device__ float g_v[(size_t)BQ * S_LEN * KVDIM];           // 17 MB
__device__ float g_attn[(size_t)BQ * S_LEN * QDIM];         // 67 MB
__device__ float g_scores[(size_t)BQ * NH * S_LEN * S_LEN]; // 1 GB

// ---------------- small helpers ----------------
__device__ __forceinline__ uint32_t f2tf(float x) {
    uint32_t r;
    asm("cvt.rna.tf32.f32 %0, %1;" : "=r"(r) : "f"(x));
    return r;
}

__device__ __forceinline__ void mma8(float* c, const uint32_t* a, const uint32_t* b) {
    asm volatile(
        "mma.sync.aligned.m16n8k8.row.col.f32.tf32.tf32.f32 "
        "{%0,%1,%2,%3},{%4,%5,%6,%7},{%8,%9},{%0,%1,%2,%3};"
        : "+f"(c[0]), "+f"(c[1]), "+f"(c[2]), "+f"(c[3])
        : "r"(a[0]), "r"(a[1]), "r"(a[2]), "r"(a[3]), "r"(b[0]), "r"(b[1]));
}

__device__ __forceinline__ void cpasync16(uint32_t dst, const void* src) {
    asm volatile("cp.async.cg.shared.global [%0], [%1], 16;" :: "r"(dst), "l"(src));
}
__device__ __forceinline__ void cp_commit() { asm volatile("cp.async.commit_group;"); }
__device__ __forceinline__ void cp_wait0()  { asm volatile("cp.async.wait_group 0;"); }

#define NEG_INF __int_as_float(0xff800000)

// ---------------- generic NT GEMM body: C[M,N] = A[M,K] @ B[N,K]^T (+bias / +scale&mask) ----------------
// Block tile 128x128x32, 256 threads, 8 warps (2x4), warp tile 64x32.
// EPI: 0 = plain (+ optional bias[n]), 1 = scores (scale + causal -inf)
template <int EPI>
__device__ __forceinline__ void gemm_nt_body(const float* __restrict__ A, int lda,
                                             const float* __restrict__ Bm, int ldb,
                                             float* __restrict__ C, int ldc,
                                             const float* __restrict__ bias, int K) {
    __shared__ float As[128 * 36];
    __shared__ float Bs[128 * 36];

    const int tid = threadIdx.x;
    const int rowBase = blockIdx.y * 128;
    const int colBase = blockIdx.x * 128;
    const int lane = tid & 31, wid = tid >> 5;
    const int wm = wid >> 2, wn = wid & 3;
    const int gid = lane >> 2, tg = lane & 3;

    float acc[4][4][4];
#pragma unroll
    for (int i = 0; i < 4; i++)
#pragma unroll
        for (int j = 0; j < 4; j++)
#pragma unroll
            for (int q = 0; q < 4; q++) acc[i][j][q] = 0.f;

    const int nK = K >> 5;
    const int acol = (tid & 7) * 4;   // 0..28
    const int arow0 = tid >> 3;       // 0..31, +r*32

    uint32_t sAs = (uint32_t)__cvta_generic_to_shared(As);
    uint32_t sBs = (uint32_t)__cvta_generic_to_shared(Bs);

    for (int kt = 0; kt < nK; kt++) {
        const float* Ag = A + (size_t)rowBase * lda + kt * 32;
        const float* Bg = Bm + (size_t)colBase * ldb + kt * 32;
#pragma unroll
        for (int r = 0; r < 4; r++) {
            int rr = arow0 + r * 32;
            cpasync16(sAs + (uint32_t)(rr * 36 + acol) * 4, Ag + (size_t)rr * lda + acol);
            cpasync16(sBs + (uint32_t)(rr * 36 + acol) * 4, Bg + (size_t)rr * ldb + acol);
        }
        cp_commit();
        cp_wait0();
        __syncthreads();

#pragma unroll
        for (int kk = 0; kk < 4; kk++) {
            uint32_t af[4][4], bf[4][2];
#pragma unroll
            for (int mi = 0; mi < 4; mi++) {
                int r0 = wm * 64 + mi * 16 + gid;
                int c0 = kk * 8 + tg;
                af[mi][0] = f2tf(As[r0 * 36 + c0]);
                af[mi][1] = f2tf(As[(r0 + 8) * 36 + c0]);
                af[mi][2] = f2tf(As[r0 * 36 + c0 + 4]);
                af[mi][3] = f2tf(As[(r0 + 8) * 36 + c0 + 4]);
            }
#pragma unroll
            for (int ni = 0; ni < 4; ni++) {
                int cb = wn * 32 + ni * 8 + gid;
                bf[ni][0] = f2tf(Bs[cb * 36 + kk * 8 + tg]);
                bf[ni][1] = f2tf(Bs[cb * 36 + kk * 8 + tg + 4]);
            }
#pragma unroll
            for (int mi = 0; mi < 4; mi++)
#pragma unroll
                for (int ni = 0; ni < 4; ni++) mma8(acc[mi][ni], af[mi], bf[ni]);
        }
        __syncthreads();
    }

    // epilogue
#pragma unroll
    for (int mi = 0; mi < 4; mi++) {
        int row = rowBase + wm * 64 + mi * 16 + gid;
#pragma unroll
        for (int ni = 0; ni < 4; ni++) {
            int col = colBase + wn * 32 + ni * 8 + 2 * tg;
            float v0 = acc[mi][ni][0], v1 = acc[mi][ni][1];
            float v2 = acc[mi][ni][2], v3 = acc[mi][ni][3];
            if (EPI == 0) {
                if (bias) {
                    float b0 = __ldg(bias + col), b1 = __ldg(bias + col + 1);
                    v0 += b0; v1 += b1; v2 += b0; v3 += b1;
                }
            } else {
                v0 *= ATT_SCALE; v1 *= ATT_SCALE; v2 *= ATT_SCALE; v3 *= ATT_SCALE;
                if (col     > row)     v0 = NEG_INF;
                if (col + 1 > row)     v1 = NEG_INF;
                if (col     > row + 8) v2 = NEG_INF;
                if (col + 1 > row + 8) v3 = NEG_INF;
            }
            *(float2*)(C + (size_t)row * ldc + col)       = make_float2(v0, v1);
            *(float2*)(C + (size_t)(row + 8) * ldc + col) = make_float2(v2, v3);
        }
    }
}

// ---------------- NN GEMM body for P@V: C[M,N] = A[M,K] @ B[K,N] ----------------
// BN = 128 (full head dim tile). k-loop clipped by caller-visible causal bound.
__device__ __forceinline__ void gemm_pv_body(const float* __restrict__ A, int lda,
                                             const float* __restrict__ Bm, int ldb,
                                             float* __restrict__ C, int ldc) {
    __shared__ float As[128 * 36];
    __shared__ float Bs[32 * 136];

    const int tid = threadIdx.x;
    const int rowBase = blockIdx.y * 128;
    const int lane = tid & 31, wid = tid >> 5;
    const int wm = wid >> 2, wn = wid & 3;
    const int gid = lane >> 2, tg = lane & 3;

    float acc[4][4][4];
#pragma unroll
    for (int i = 0; i < 4; i++)
#pragma unroll
        for (int j = 0; j < 4; j++)
#pragma unroll
            for (int q = 0; q < 4; q++) acc[i][j][q] = 0.f;

    const int nK = (rowBase + 128) >> 5;  // causal: P is zero beyond row tile's diagonal
    const int acol = (tid & 7) * 4;
    const int arow0 = tid >> 3;
    const int bc4 = (tid & 31) * 4;
    const int brow0 = tid >> 5;  // +r*8

    uint32_t sAs = (uint32_t)__cvta_generic_to_shared(As);
    uint32_t sBs = (uint32_t)__cvta_generic_to_shared(Bs);

    for (int kt = 0; kt < nK; kt++) {
        const float* Ag = A + (size_t)rowBase * lda + kt * 32;
        const float* Bg = Bm + (size_t)(kt * 32) * ldb;
#pragma unroll
        for (int r = 0; r < 4; r++) {
            int rr = arow0 + r * 32;
            cpasync16(sAs + (uint32_t)(rr * 36 + acol) * 4, Ag + (size_t)rr * lda + acol);
            int br = brow0 + r * 8;
            cpasync16(sBs + (uint32_t)(br * 136 + bc4) * 4, Bg + (size_t)br * ldb + bc4);
        }
        cp_commit();
        cp_wait0();
        __syncthreads();

#pragma unroll
        for (int kk = 0; kk < 4; kk++) {
            uint32_t af[4][4], bf[4][2];
#pragma unroll
            for (int mi = 0; mi < 4; mi++) {
                int r0 = wm * 64 + mi * 16 + gid;
                int c0 = kk * 8 + tg;
                af[mi][0] = f2tf(As[r0 * 36 + c0]);
                af[mi][1] = f2tf(As[(r0 + 8) * 36 + c0]);
                af[mi][2] = f2tf(As[r0 * 36 + c0 + 4]);
                af[mi][3] = f2tf(As[(r0 + 8) * 36 + c0 + 4]);
            }
#pragma unroll
            for (int ni = 0; ni < 4; ni++) {
                int cb = wn * 32 + ni * 8 + gid;
                bf[ni][0] = f2tf(Bs[(kk * 8 + tg) * 136 + cb]);
                bf[ni][1] = f2tf(Bs[(kk * 8 + tg + 4) * 136 + cb]);
            }
#pragma unroll
            for (int mi = 0; mi < 4; mi++)
#pragma unroll
                for (int ni = 0; ni < 4; ni++) mma8(acc[mi][ni], af[mi], bf[ni]);
        }
        __syncthreads();
    }

#pragma unroll
    for (int mi = 0; mi < 4; mi++) {
        int row = rowBase + wm * 64 + mi * 16 + gid;
#pragma unroll
        for (int ni = 0; ni < 4; ni++) {
            int col = wn * 32 + ni * 8 + 2 * tg;
            *(float2*)(C + (size_t)row * ldc + col) =
                make_float2(acc[mi][ni][0], acc[mi][ni][1]);
            *(float2*)(C + (size_t)(row + 8) * ldc + col) =
                make_float2(acc[mi][ni][2], acc[mi][ni][3]);
        }
    }
}

// ---------------- kernels ----------------
__global__ void __launch_bounds__(256, 2) k_gemm_q(const float* __restrict__ x,
                                                   const float* __restrict__ w) {
    gemm_nt_body<0>(x, DM, w, DM, g_q, QDIM, nullptr, DM);
}
__global__ void __launch_bounds__(256, 2) k_gemm_k(const float* __restrict__ x,
                                                   const float* __restrict__ w,
                                                   const float* __restrict__ bias) {
    gemm_nt_body<0>(x, DM, w, DM, g_k, KVDIM, bias, DM);
}
__global__ void __launch_bounds__(256, 2) k_gemm_v(const float* __restrict__ x,
                                                   const float* __restrict__ w) {
    gemm_nt_body<0>(x, DM, w, DM, g_v, KVDIM, nullptr, DM);
}

__global__ void __launch_bounds__(256) k_rope() {
    int idx = blockIdx.x * 256 + threadIdx.x;
    const int NQp = BQ * S_LEN * NH * (HDIM / 2);   // 8388608
    const int NKp = BQ * S_LEN * NKV * (HDIM / 2);  // 2097152
    float* p;
    int s, d;
    if (idx < NQp) {
        d = idx & 63;
        int h = (idx >> 6) & (NH - 1);
        int srow = idx >> 11;  // b*S + s
        s = srow & (S_LEN - 1);
        p = g_q + ((size_t)srow * NH + h) * HDIM + 2 * d;
    } else {
        idx -= NQp;
        if (idx >= NKp) return;
        d = idx & 63;
        int h = (idx >> 6) & (NKV - 1);
        int srow = idx >> 9;
        s = srow & (S_LEN - 1);
        p = g_k + ((size_t)srow * NKV + h) * HDIM + 2 * d;
    }
    float e = (float)d * (1.f / 64.f);
    float theta = expf(-LN_BASE * e);
    float ang = (float)s * theta;
    float c = cosf(ang), sn = sinf(ang);
    float x1 = p[0], x2 = p[1];
    p[0] = x1 * c - x2 * sn;
    p[1] = x1 * sn + x2 * c;
}

__global__ void __launch_bounds__(256, 2) k_scores() {
    // early-exit fully-masked tiles (above the diagonal): ~47% compute skipped
    if ((int)blockIdx.x * 128 > (int)blockIdx.y * 128 + 127) return;
    int z = blockIdx.z;           // b*NH + h
    int b = z >> 5, h = z & 31;
    gemm_nt_body<1>(g_q + (size_t)b * S_LEN * QDIM + h * HDIM, QDIM,
                    g_k + (size_t)b * S_LEN * KVDIM + (h >> 2) * HDIM, KVDIM,
                    g_scores + (size_t)z * S_LEN * S_LEN, S_LEN, nullptr, HDIM);
}

__global__ void __launch_bounds__(256) k_softmax() {
    int rowid = blockIdx.x * 8 + (threadIdx.x >> 5);
    int lane = threadIdx.x & 31;
    int z = rowid >> 11, r = rowid & (S_LEN - 1);
    float* row = g_scores + (size_t)z * S_LEN * S_LEN + (size_t)r * S_LEN;
    int n = r + 1;
    float mx = -3.4e38f;
    for (int i = lane; i < n; i += 32) mx = fmaxf(mx, row[i]);
#pragma unroll
    for (int o = 16; o; o >>= 1) mx = fmaxf(mx, __shfl_xor_sync(0xffffffffu, mx, o));
    float sum = 0.f;
    for (int i = lane; i < n; i += 32) {
        float ev = expf(row[i] - mx);
        row[i] = ev;
        sum += ev;
    }
#pragma unroll
    for (int o = 16; o; o >>= 1) sum += __shfl_xor_sync(0xffffffffu, sum, o);
    float inv = 1.f / sum;
    for (int i = lane; i < n; i += 32) row[i] *= inv;
    for (int i = n + lane; i < S_LEN; i += 32) row[i] = 0.f;  // zeros for PV GEMM
}

__global__ void __launch_bounds__(256, 2) k_pv() {
    int z = blockIdx.z;
    int b = z >> 5, h = z & 31;
    gemm_pv_body(g_scores + (size_t)z * S_LEN * S_LEN, S_LEN,
                 g_v + (size_t)b * S_LEN * KVDIM + (h >> 2) * HDIM, KVDIM,
                 g_attn + (size_t)b * S_LEN * QDIM + h * HDIM, QDIM);
}

__global__ void __launch_bounds__(256, 2) k_oproj(const float* __restrict__ w,
                                                  float* __restrict__ out) {
    gemm_nt_body<0>(g_attn, QDIM, w, QDIM, out, DM, nullptr, QDIM);
}

// ---------------- entry ----------------
extern "C" void kernel_launch(void* const* d_in, const int* in_sizes, int n_in,
                              void* d_out, int out_size) {
    const float* x  = (const float*)d_in[0];
    // d_in[1] = mask (tril) — causality hardcoded, not needed
    const float* wq = (const float*)d_in[2];
    const float* wk = (const float*)d_in[3];
    const float* bk = (const float*)d_in[4];
    const float* wv = (const float*)d_in[5];
    const float* wo = (const float*)d_in[6];
    float* out = (float*)d_out;

    const int M = BQ * S_LEN;  // 4096

    k_gemm_q<<<dim3(QDIM / 128, M / 128), 256>>>(x, wq);
    k_gemm_k<<<dim3(KVDIM / 128, M / 128), 256>>>(x, wk, bk);
    k_gemm_v<<<dim3(KVDIM / 128, M / 128), 256>>>(x, wv);

    const int rope_threads = BQ * S_LEN * (NH + NKV) * (HDIM / 2);
    k_rope<<<(rope_threads + 255) / 256, 256>>>();

    k_scores<<<dim3(S_LEN / 128, S_LEN / 128, BQ * NH), 256>>>();
    k_softmax<<<(BQ * NH * S_LEN) / 8, 256>>>();
    k_pv<<<dim3(1, S_LEN / 128, BQ * NH), 256>>>();

    k_oproj<<<dim3(DM / 128, M / 128), 256>>>(wo, out);
}

// round 4
// speedup vs baseline: 1.1689x; 1.1689x over previous
#include <cuda_runtime.h>
#include <cstdint>
#include <cstddef>

// ---------------- problem constants ----------------
#define BQ    2
#define S_LEN 2048
#define DM    5120
#define NH    32
#define NKV   8
#define HDIM  128
#define QDIM  (NH * HDIM)    // 4096
#define KVDIM (NKV * HDIM)   // 1024
#define ATT_SCALE 0.08838834764831845f
#define LN_BASE 13.815510557964274f   // ln(1e6)

// ---------------- scratch (device globals; allocation-free rule) ----------------
__device__ float g_q[(size_t)BQ * S_LEN * QDIM];            // 67 MB
__device__ float g_k[(size_t)BQ * S_LEN * KVDIM];           // 17 MB
__device__ float g_v[(size_t)BQ * S_LEN * KVDIM];           // 17 MB
__device__ float g_attn[(size_t)BQ * S_LEN * QDIM];         // 67 MB

// ---------------- small helpers ----------------
__device__ __forceinline__ uint32_t f2tf(float x) {
    uint32_t r;
    asm("cvt.rna.tf32.f32 %0, %1;" : "=r"(r) : "f"(x));
    return r;
}

__device__ __forceinline__ void mma8(float* c, const uint32_t* a, const uint32_t* b) {
    asm volatile(
        "mma.sync.aligned.m16n8k8.row.col.f32.tf32.tf32.f32 "
        "{%0,%1,%2,%3},{%4,%5,%6,%7},{%8,%9},{%0,%1,%2,%3};"
        : "+f"(c[0]), "+f"(c[1]), "+f"(c[2]), "+f"(c[3])
        : "r"(a[0]), "r"(a[1]), "r"(a[2]), "r"(a[3]), "r"(b[0]), "r"(b[1]));
}

__device__ __forceinline__ void cpasync16(uint32_t dst, const void* src) {
    asm volatile("cp.async.cg.shared.global [%0], [%1], 16;" :: "r"(dst), "l"(src));
}
__device__ __forceinline__ void cp_commit() { asm volatile("cp.async.commit_group;"); }
template <int N>
__device__ __forceinline__ void cp_wait() { asm volatile("cp.async.wait_group %0;" :: "n"(N)); }

#define NEG_INF __int_as_float(0xff800000)

// RoPE rotation of the pair (v0 at even col, v1 at odd col), row = b*S + s.
// Identical fp32 formula chain as the reference path (expf/cosf/sinf).
__device__ __forceinline__ void rope_pair(float& v0, float& v1, int row, int col) {
    int s = row & (S_LEN - 1);
    int d = (col & (HDIM - 1)) >> 1;          // pair index 0..63
    float e = (float)d * (1.f / 64.f);
    float theta = expf(-LN_BASE * e);
    float ang = (float)s * theta;
    float c = cosf(ang), sn = sinf(ang);
    float x1 = v0, x2 = v1;
    v0 = x1 * c - x2 * sn;
    v1 = x1 * sn + x2 * c;
}

// =====================================================================
// Pipelined NT GEMM: C[M,N] = A[M,K] @ B[N,K]^T (+bias) (+RoPE epilogue)
// Block tile 128x128x32, 256 threads, 8 warps (2x4), warp tile 64x32.
// 2-stage cp.async double buffering. Dynamic smem: 2*2*128*36*4 = 73728 B.
// =====================================================================
template <int ROPE>
__device__ __forceinline__ void gemm_nt_body(const float* __restrict__ A, int lda,
                                             const float* __restrict__ Bm, int ldb,
                                             float* __restrict__ C, int ldc,
                                             const float* __restrict__ bias, int K) {
    extern __shared__ float sm[];
    float* As = sm;           // [2][128*36]
    float* Bs = sm + 9216;    // [2][128*36]

    const int tid = threadIdx.x;
    const int rowBase = blockIdx.y * 128;
    const int colBase = blockIdx.x * 128;
    const int lane = tid & 31, wid = tid >> 5;
    const int wm = wid >> 2, wn = wid & 3;
    const int gid = lane >> 2, tg = lane & 3;

    float acc[4][4][4];
#pragma unroll
    for (int i = 0; i < 4; i++)
#pragma unroll
        for (int j = 0; j < 4; j++)
#pragma unroll
            for (int q = 0; q < 4; q++) acc[i][j][q] = 0.f;

    const int nK = K >> 5;
    const int acol = (tid & 7) * 4;
    const int arow0 = tid >> 3;

    uint32_t sAs = (uint32_t)__cvta_generic_to_shared(As);
    uint32_t sBs = (uint32_t)__cvta_generic_to_shared(Bs);

    auto issue = [&](int kt, int st) {
        const float* Ag = A + (size_t)rowBase * lda + kt * 32;
        const float* Bg = Bm + (size_t)colBase * ldb + kt * 32;
#pragma unroll
        for (int r = 0; r < 4; r++) {
            int rr = arow0 + r * 32;
            cpasync16(sAs + (uint32_t)(st * 4608 + rr * 36 + acol) * 4,
                      Ag + (size_t)rr * lda + acol);
            cpasync16(sBs + (uint32_t)(st * 4608 + rr * 36 + acol) * 4,
                      Bg + (size_t)rr * ldb + acol);
        }
        cp_commit();
    };

    issue(0, 0);
    int st = 0;
    for (int kt = 0; kt < nK; kt++) {
        if (kt + 1 < nK) { issue(kt + 1, st ^ 1); cp_wait<1>(); }
        else             { cp_wait<0>(); }
        __syncthreads();
        const float* Ab = As + st * 4608;
        const float* Bb = Bs + st * 4608;
#pragma unroll
        for (int kk = 0; kk < 4; kk++) {
            uint32_t af[4][4], bf[4][2];
#pragma unroll
            for (int mi = 0; mi < 4; mi++) {
                int r0 = wm * 64 + mi * 16 + gid;
                int c0 = kk * 8 + tg;
                af[mi][0] = f2tf(Ab[r0 * 36 + c0]);
                af[mi][1] = f2tf(Ab[(r0 + 8) * 36 + c0]);
                af[mi][2] = f2tf(Ab[r0 * 36 + c0 + 4]);
                af[mi][3] = f2tf(Ab[(r0 + 8) * 36 + c0 + 4]);
            }
#pragma unroll
            for (int ni = 0; ni < 4; ni++) {
                int cb = wn * 32 + ni * 8 + gid;
                bf[ni][0] = f2tf(Bb[cb * 36 + kk * 8 + tg]);
                bf[ni][1] = f2tf(Bb[cb * 36 + kk * 8 + tg + 4]);
            }
#pragma unroll
            for (int mi = 0; mi < 4; mi++)
#pragma unroll
                for (int ni = 0; ni < 4; ni++) mma8(acc[mi][ni], af[mi], bf[ni]);
        }
        __syncthreads();
        st ^= 1;
    }

#pragma unroll
    for (int mi = 0; mi < 4; mi++) {
        int row = rowBase + wm * 64 + mi * 16 + gid;
#pragma unroll
        for (int ni = 0; ni < 4; ni++) {
            int col = colBase + wn * 32 + ni * 8 + 2 * tg;
            float v0 = acc[mi][ni][0], v1 = acc[mi][ni][1];
            float v2 = acc[mi][ni][2], v3 = acc[mi][ni][3];
            if (bias) {
                float b0 = __ldg(bias + col), b1 = __ldg(bias + col + 1);
                v0 += b0; v1 += b1; v2 += b0; v3 += b1;
            }
            if (ROPE) {
                rope_pair(v0, v1, row, col);
                rope_pair(v2, v3, row + 8, col);
            }
            *(float2*)(C + (size_t)row * ldc + col)       = make_float2(v0, v1);
            *(float2*)(C + (size_t)(row + 8) * ldc + col) = make_float2(v2, v3);
        }
    }
}

__global__ void __launch_bounds__(256, 2) k_gemm_q(const float* __restrict__ x,
                                                   const float* __restrict__ w) {
    gemm_nt_body<1>(x, DM, w, DM, g_q, QDIM, nullptr, DM);
}
__global__ void __launch_bounds__(256, 2) k_gemm_k(const float* __restrict__ x,
                                                   const float* __restrict__ w,
                                                   const float* __restrict__ bias) {
    gemm_nt_body<1>(x, DM, w, DM, g_k, KVDIM, bias, DM);
}
__global__ void __launch_bounds__(256, 2) k_gemm_v(const float* __restrict__ x,
                                                   const float* __restrict__ w) {
    gemm_nt_body<0>(x, DM, w, DM, g_v, KVDIM, nullptr, DM);
}
__global__ void __launch_bounds__(256, 2) k_oproj(const float* __restrict__ w,
                                                  float* __restrict__ out) {
    gemm_nt_body<0>(g_attn, QDIM, w, QDIM, out, DM, nullptr, QDIM);
}

// =====================================================================
// Fused flash attention: per CTA = (b,h, 128-row Q tile).
// S = Q@K^T (tf32 mma) -> online softmax in regs -> P via SMEM -> P@V.
// Dynamic smem layout (floats):
//   Qs [128][132]      @ 0       (16896)
//   Ks [2][128][36]    @ 16896   ( 9216)
//   Ps [128][132]      @ 26112   (16896)
//   Vs [2][32][136]    @ 43008   ( 8704)
//   redmx [4][128]     @ 51712   (  512)
//   redsm [4][128]     @ 52224   (  512)
// total 52736 floats = 210944 B
// =====================================================================
__global__ void __launch_bounds__(256) k_flash() {
    extern __shared__ float sm[];
    float* Qs = sm;
    float* Ks = sm + 16896;
    float* Ps = sm + 26112;
    float* Vs = sm + 43008;
    float* redmx = sm + 51712;
    float* redsm = sm + 52224;

    const int tid = threadIdx.x;
    const int lane = tid & 31, wid = tid >> 5;
    const int wm = wid >> 2, wn = wid & 3;
    const int gid = lane >> 2, tg = lane & 3;
    const int qt = (int)gridDim.x - 1 - (int)blockIdx.x;   // big tiles first
    const int z = blockIdx.y;
    const int b = z >> 5, h = z & 31;

    const float* Qg = g_q + ((size_t)(b * S_LEN + qt * 128)) * QDIM + h * HDIM;
    const float* Kg = g_k + (size_t)(b * S_LEN) * KVDIM + (h >> 2) * HDIM;
    const float* Vg = g_v + (size_t)(b * S_LEN) * KVDIM + (h >> 2) * HDIM;

    uint32_t sQs = (uint32_t)__cvta_generic_to_shared(Qs);
    uint32_t sKs = (uint32_t)__cvta_generic_to_shared(Ks);
    uint32_t sVs = (uint32_t)__cvta_generic_to_shared(Vs);

    // Q tile load (one cp.async group, stays resident)
#pragma unroll
    for (int i = 0; i < 16; i++) {
        int id = i * 256 + tid;
        int r = id >> 5, seg = id & 31;
        cpasync16(sQs + (uint32_t)(r * 132 + seg * 4) * 4,
                  Qg + (size_t)r * QDIM + seg * 4);
    }
    cp_commit();

    float o[4][4][4];
    float m[4][2], l[4][2];
#pragma unroll
    for (int mi = 0; mi < 4; mi++) {
#pragma unroll
        for (int ni = 0; ni < 4; ni++)
#pragma unroll
            for (int q = 0; q < 4; q++) o[mi][ni][q] = 0.f;
        m[mi][0] = NEG_INF; m[mi][1] = NEG_INF;
        l[mi][0] = 0.f;     l[mi][1] = 0.f;
    }

    auto issueK = [&](int j, int kt, int st) {
#pragma unroll
        for (int i = 0; i < 4; i++) {
            int id = i * 256 + tid;
            int r = id >> 3, seg = id & 7;
            cpasync16(sKs + (uint32_t)(st * 4608 + r * 36 + seg * 4) * 4,
                      Kg + (size_t)(j * 128 + r) * KVDIM + kt * 32 + seg * 4);
        }
        cp_commit();
    };
    auto issueV = [&](int j, int kt, int st) {
#pragma unroll
        for (int i = 0; i < 4; i++) {
            int id = i * 256 + tid;
            int r = id >> 5, seg = id & 31;
            cpasync16(sVs + (uint32_t)(st * 4352 + r * 136 + seg * 4) * 4,
                      Vg + (size_t)(j * 128 + kt * 32 + r) * KVDIM + seg * 4);
        }
        cp_commit();
    };

    float s[4][4][4];

    auto computeS = [&](int st, int kt) {
        const float* kb = Ks + st * 4608;
#pragma unroll
        for (int kk = 0; kk < 4; kk++) {
            uint32_t af[4][4], bf[4][2];
#pragma unroll
            for (int mi = 0; mi < 4; mi++) {
                int r0 = wm * 64 + mi * 16 + gid;
                int c0 = kt * 32 + kk * 8 + tg;
                af[mi][0] = f2tf(Qs[r0 * 132 + c0]);
                af[mi][1] = f2tf(Qs[(r0 + 8) * 132 + c0]);
                af[mi][2] = f2tf(Qs[r0 * 132 + c0 + 4]);
                af[mi][3] = f2tf(Qs[(r0 + 8) * 132 + c0 + 4]);
            }
#pragma unroll
            for (int ni = 0; ni < 4; ni++) {
                int cb = wn * 32 + ni * 8 + gid;
                bf[ni][0] = f2tf(kb[cb * 36 + kk * 8 + tg]);
                bf[ni][1] = f2tf(kb[cb * 36 + kk * 8 + tg + 4]);
            }
#pragma unroll
            for (int mi = 0; mi < 4; mi++)
#pragma unroll
                for (int ni = 0; ni < 4; ni++) mma8(s[mi][ni], af[mi], bf[ni]);
        }
    };

    auto computePV = [&](int st, int kt) {
        const float* vb = Vs + st * 4352;
#pragma unroll
        for (int kk = 0; kk < 4; kk++) {
            uint32_t af[4][4], bf[4][2];
#pragma unroll
            for (int mi = 0; mi < 4; mi++) {
                int r0 = wm * 64 + mi * 16 + gid;
                int c0 = kt * 32 + kk * 8 + tg;
                af[mi][0] = f2tf(Ps[r0 * 132 + c0]);
                af[mi][1] = f2tf(Ps[(r0 + 8) * 132 + c0]);
                af[mi][2] = f2tf(Ps[r0 * 132 + c0 + 4]);
                af[mi][3] = f2tf(Ps[(r0 + 8) * 132 + c0 + 4]);
            }
#pragma unroll
            for (int ni = 0; ni < 4; ni++) {
                int cb = wn * 32 + ni * 8 + gid;
                bf[ni][0] = f2tf(vb[(kk * 8 + tg) * 136 + cb]);
                bf[ni][1] = f2tf(vb[(kk * 8 + tg + 4) * 136 + cb]);
            }
#pragma unroll
            for (int mi = 0; mi < 4; mi++)
#pragma unroll
                for (int ni = 0; ni < 4; ni++) mma8(o[mi][ni], af[mi], bf[ni]);
        }
    };

    for (int j = 0; j <= qt; j++) {
#pragma unroll
        for (int mi = 0; mi < 4; mi++)
#pragma unroll
            for (int ni = 0; ni < 4; ni++)
#pragma unroll
                for (int q = 0; q < 4; q++) s[mi][ni][q] = 0.f;

        // ---- S = Q @ K^T, double-buffered; V chunk 0 prefetched mid-phase
        issueK(j, 0, 0);
        issueK(j, 1, 1);
        cp_wait<1>(); __syncthreads(); computeS(0, 0); __syncthreads();
        issueK(j, 2, 0);
        cp_wait<1>(); __syncthreads(); computeS(1, 1); __syncthreads();
        issueK(j, 3, 1);
        issueV(j, 0, 0);
        cp_wait<2>(); __syncthreads(); computeS(0, 2); __syncthreads();
        cp_wait<1>(); __syncthreads(); computeS(1, 3);

        // ---- scale + causal mask + thread-local row max
        float mx[4][2];
#pragma unroll
        for (int mi = 0; mi < 4; mi++) {
            mx[mi][0] = NEG_INF; mx[mi][1] = NEG_INF;
            int rl = wm * 64 + mi * 16 + gid;
#pragma unroll
            for (int ni = 0; ni < 4; ni++) {
                int cl = wn * 32 + ni * 8 + 2 * tg;
                float v0 = s[mi][ni][0] * ATT_SCALE, v1 = s[mi][ni][1] * ATT_SCALE;
                float v2 = s[mi][ni][2] * ATT_SCALE, v3 = s[mi][ni][3] * ATT_SCALE;
                if (j == qt) {
                    if (cl     > rl)     v0 = NEG_INF;
                    if (cl + 1 > rl)     v1 = NEG_INF;
                    if (cl     > rl + 8) v2 = NEG_INF;
                    if (cl + 1 > rl + 8) v3 = NEG_INF;
                }
                s[mi][ni][0] = v0; s[mi][ni][1] = v1;
                s[mi][ni][2] = v2; s[mi][ni][3] = v3;
                mx[mi][0] = fmaxf(mx[mi][0], fmaxf(v0, v1));
                mx[mi][1] = fmaxf(mx[mi][1], fmaxf(v2, v3));
            }
        }
#pragma unroll
        for (int mi = 0; mi < 4; mi++)
#pragma unroll
            for (int q2 = 0; q2 < 2; q2++) {
                float v = mx[mi][q2];
                v = fmaxf(v, __shfl_xor_sync(0xffffffffu, v, 1));
                v = fmaxf(v, __shfl_xor_sync(0xffffffffu, v, 2));
                mx[mi][q2] = v;
            }
        if (tg == 0) {
#pragma unroll
            for (int mi = 0; mi < 4; mi++)
#pragma unroll
                for (int q2 = 0; q2 < 2; q2++)
                    redmx[wn * 128 + wm * 64 + mi * 16 + gid + q2 * 8] = mx[mi][q2];
        }
        __syncthreads();

        float fac[4][2];
#pragma unroll
        for (int mi = 0; mi < 4; mi++)
#pragma unroll
            for (int q2 = 0; q2 < 2; q2++) {
                int r = wm * 64 + mi * 16 + gid + q2 * 8;
                float Mt = fmaxf(fmaxf(redmx[r], redmx[128 + r]),
                                 fmaxf(redmx[256 + r], redmx[384 + r]));
                float mn = fmaxf(m[mi][q2], Mt);
                fac[mi][q2] = expf(m[mi][q2] - mn);
                m[mi][q2] = mn;
            }

        // ---- P = exp(s - m), store to smem; rescale O; partial row sums
        float ps[4][2];
#pragma unroll
        for (int mi = 0; mi < 4; mi++) { ps[mi][0] = 0.f; ps[mi][1] = 0.f; }
#pragma unroll
        for (int mi = 0; mi < 4; mi++) {
            int rl = wm * 64 + mi * 16 + gid;
#pragma unroll
            for (int ni = 0; ni < 4; ni++) {
                int cl = wn * 32 + ni * 8 + 2 * tg;
                float p0 = expf(s[mi][ni][0] - m[mi][0]);
                float p1 = expf(s[mi][ni][1] - m[mi][0]);
                float p2 = expf(s[mi][ni][2] - m[mi][1]);
                float p3 = expf(s[mi][ni][3] - m[mi][1]);
                ps[mi][0] += p0 + p1;
                ps[mi][1] += p2 + p3;
                *(float2*)&Ps[rl * 132 + cl]       = make_float2(p0, p1);
                *(float2*)&Ps[(rl + 8) * 132 + cl] = make_float2(p2, p3);
                o[mi][ni][0] *= fac[mi][0]; o[mi][ni][1] *= fac[mi][0];
                o[mi][ni][2] *= fac[mi][1]; o[mi][ni][3] *= fac[mi][1];
            }
        }
#pragma unroll
        for (int mi = 0; mi < 4; mi++)
#pragma unroll
            for (int q2 = 0; q2 < 2; q2++) {
                float v = ps[mi][q2];
                v += __shfl_xor_sync(0xffffffffu, v, 1);
                v += __shfl_xor_sync(0xffffffffu, v, 2);
                ps[mi][q2] = v;
            }
        if (tg == 0) {
#pragma unroll
            for (int mi = 0; mi < 4; mi++)
#pragma unroll
                for (int q2 = 0; q2 < 2; q2++)
                    redsm[wn * 128 + wm * 64 + mi * 16 + gid + q2 * 8] = ps[mi][q2];
        }
        __syncthreads();   // Ps + redsm visible
#pragma unroll
        for (int mi = 0; mi < 4; mi++)
#pragma unroll
            for (int q2 = 0; q2 < 2; q2++) {
                int r = wm * 64 + mi * 16 + gid + q2 * 8;
                l[mi][q2] = l[mi][q2] * fac[mi][q2] +
                            (redsm[r] + redsm[128 + r] + redsm[256 + r] + redsm[384 + r]);
            }

        // ---- O += P @ V, double-buffered (V0 already in flight)
        issueV(j, 1, 1);
        cp_wait<1>(); __syncthreads(); computePV(0, 0); __syncthreads();
        issueV(j, 2, 0);
        cp_wait<1>(); __syncthreads(); computePV(1, 1); __syncthreads();
        issueV(j, 3, 1);
        cp_wait<1>(); __syncthreads(); computePV(0, 2); __syncthreads();
        cp_wait<0>(); __syncthreads(); computePV(1, 3);
        __syncthreads();
    }

    // ---- epilogue: O / l -> g_attn
#pragma unroll
    for (int mi = 0; mi < 4; mi++) {
        float inv0 = 1.f / l[mi][0];
        float inv1 = 1.f / l[mi][1];
        int row = qt * 128 + wm * 64 + mi * 16 + gid;
        float* dst = g_attn + ((size_t)(b * S_LEN) + row) * QDIM + h * HDIM;
#pragma unroll
        for (int ni = 0; ni < 4; ni++) {
            int col = wn * 32 + ni * 8 + 2 * tg;
            *(float2*)(dst + col) =
                make_float2(o[mi][ni][0] * inv0, o[mi][ni][1] * inv0);
            *(float2*)(dst + (size_t)8 * QDIM + col) =
                make_float2(o[mi][ni][2] * inv1, o[mi][ni][3] * inv1);
        }
    }
}

// ---------------- entry ----------------
extern "C" void kernel_launch(void* const* d_in, const int* in_sizes, int n_in,
                              void* d_out, int out_size) {
    const float* x  = (const float*)d_in[0];
    // d_in[1] = mask (tril) — causality hardcoded
    const float* wq = (const float*)d_in[2];
    const float* wk = (const float*)d_in[3];
    const float* bk = (const float*)d_in[4];
    const float* wv = (const float*)d_in[5];
    const float* wo = (const float*)d_in[6];
    float* out = (float*)d_out;

    const int PROJ_SMEM  = 73728;
    const int FLASH_SMEM = 210944;
    cudaFuncSetAttribute(k_gemm_q, cudaFuncAttributeMaxDynamicSharedMemorySize, PROJ_SMEM);
    cudaFuncSetAttribute(k_gemm_k, cudaFuncAttributeMaxDynamicSharedMemorySize, PROJ_SMEM);
    cudaFuncSetAttribute(k_gemm_v, cudaFuncAttributeMaxDynamicSharedMemorySize, PROJ_SMEM);
    cudaFuncSetAttribute(k_oproj,  cudaFuncAttributeMaxDynamicSharedMemorySize, PROJ_SMEM);
    cudaFuncSetAttribute(k_flash,  cudaFuncAttributeMaxDynamicSharedMemorySize, FLASH_SMEM);

    const int M = BQ * S_LEN;  // 4096

    k_gemm_q<<<dim3(QDIM / 128, M / 128), 256, PROJ_SMEM>>>(x, wq);
    k_gemm_k<<<dim3(KVDIM / 128, M / 128), 256, PROJ_SMEM>>>(x, wk, bk);
    k_gemm_v<<<dim3(KVDIM / 128, M / 128), 256, PROJ_SMEM>>>(x, wv);

    k_flash<<<dim3(S_LEN / 128, BQ * NH), 256, FLASH_SMEM>>>();

    k_oproj<<<dim3(DM / 128, M / 128), 256, PROJ_SMEM>>>(wo, out);
}